// round 1
// baseline (speedup 1.0000x reference)
#include <cuda_runtime.h>
#include <cuda_bf16.h>
#include <cstdint>

// Problem constants: a,b are [4096, 256] fp32; X = concat -> [8192, 256].
#define BPAIRS 4096
#define NROWS  8192
#define DCOLS  256

// Gram tiling
#define BM 128
#define BN 128
#define BK 64
#define SK 72   // padded shared stride (bf16 elems): 144B rows, conflict-free frag loads

// Scratch: normalized X in bf16, plus two fp32 accumulators [align_sum, uniform_sum]
__device__ __align__(16) __nv_bfloat16 g_X[NROWS * DCOLS];
__device__ float g_acc[2];

__global__ void k_zero() {
    g_acc[0] = 0.0f;
    g_acc[1] = 0.0f;
}

// One block per row pair r: normalize a_r, b_r (fp32), emit bf16 rows into g_X,
// and accumulate align contribution sum((a_n - b_n)^2) in fp32.
__global__ void k_norm(const float* __restrict__ A, const float* __restrict__ B) {
    int r = blockIdx.x;
    int t = threadIdx.x;           // 256 threads == DCOLS
    float a = A[r * DCOLS + t];
    float b = B[r * DCOLS + t];
    float sa = a * a, sb = b * b;
    #pragma unroll
    for (int o = 16; o; o >>= 1) {
        sa += __shfl_xor_sync(0xffffffffu, sa, o);
        sb += __shfl_xor_sync(0xffffffffu, sb, o);
    }
    __shared__ float ssa[8], ssb[8], sdd[8];
    int wid = t >> 5, lane = t & 31;
    if (lane == 0) { ssa[wid] = sa; ssb[wid] = sb; }
    __syncthreads();
    float na = 0.f, nb = 0.f;
    #pragma unroll
    for (int i = 0; i < 8; i++) { na += ssa[i]; nb += ssb[i]; }
    na = fmaxf(sqrtf(na), 1e-12f);
    nb = fmaxf(sqrtf(nb), 1e-12f);
    float an = a / na, bn = b / nb;
    g_X[r * DCOLS + t] = __float2bfloat16(an);
    g_X[(BPAIRS + r) * DCOLS + t] = __float2bfloat16(bn);
    float d = an - bn;
    float dd = d * d;
    #pragma unroll
    for (int o = 16; o; o >>= 1) dd += __shfl_xor_sync(0xffffffffu, dd, o);
    if (lane == 0) sdd[wid] = dd;
    __syncthreads();
    if (t == 0) {
        float s = 0.f;
        #pragma unroll
        for (int i = 0; i < 8; i++) s += sdd[i];
        atomicAdd(&g_acc[0], s);
    }
}

__device__ __forceinline__ void mma16816(float d[4], const uint32_t a[4], const uint32_t b[2]) {
    asm volatile(
        "mma.sync.aligned.m16n8k16.row.col.f32.bf16.bf16.f32 "
        "{%0,%1,%2,%3}, {%4,%5,%6,%7}, {%8,%9}, {%0,%1,%2,%3};\n"
        : "+f"(d[0]), "+f"(d[1]), "+f"(d[2]), "+f"(d[3])
        : "r"(a[0]), "r"(a[1]), "r"(a[2]), "r"(a[3]), "r"(b[0]), "r"(b[1]));
}

// Gram tile kernel over the upper-triangular block grid (bj >= bi).
// Each 128x128 tile: bf16 mma.sync GEMM over K=256, then fused exp(-2*d2) and
// reduction. Off-diagonal tiles weighted x2 (symmetry). Diagonal entries are
// included (exp(~0)=~1) and subtracted globally in the finalize kernel.
__global__ __launch_bounds__(256, 2) void k_gram() {
    __shared__ __align__(16) __nv_bfloat16 As[BM * SK];
    __shared__ __align__(16) __nv_bfloat16 Bs[BN * SK];
    __shared__ float sred[8];

    // decode blockIdx.x -> (bi, bj) with bj >= bi over 64x64 tile grid
    int bi = 0;
    int rem = blockIdx.x;
    int rowlen = NROWS / BM;   // 64
    while (rem >= rowlen) { rem -= rowlen; bi++; rowlen--; }
    int bj = bi + rem;
    int ai0 = bi * BM, bj0 = bj * BN;

    int tid = threadIdx.x;
    int wid = tid >> 5, lane = tid & 31;
    int wm = wid >> 1, wn = wid & 1;     // 4x2 warp grid
    int m0 = wm * 32, n0 = wn * 64;      // per-warp 32x64 output region
    int g = lane >> 2, t4 = lane & 3;

    float acc[2][8][4];
    #pragma unroll
    for (int mi = 0; mi < 2; mi++)
        #pragma unroll
        for (int ni = 0; ni < 8; ni++)
            #pragma unroll
            for (int e = 0; e < 4; e++) acc[mi][ni][e] = 0.0f;

    #pragma unroll
    for (int kb = 0; kb < DCOLS / BK; kb++) {
        // stage tiles: 128 rows x 64 bf16 each, uint4 (8 bf16) vectorized
        #pragma unroll
        for (int i = 0; i < 4; i++) {
            int idx = tid + i * 256;       // 0..1023
            int r = idx >> 3, c8 = idx & 7;
            *reinterpret_cast<uint4*>(&As[r * SK + c8 * 8]) =
                *reinterpret_cast<const uint4*>(&g_X[(ai0 + r) * DCOLS + kb * BK + c8 * 8]);
            *reinterpret_cast<uint4*>(&Bs[r * SK + c8 * 8]) =
                *reinterpret_cast<const uint4*>(&g_X[(bj0 + r) * DCOLS + kb * BK + c8 * 8]);
        }
        __syncthreads();

        #pragma unroll
        for (int ks = 0; ks < BK / 16; ks++) {
            int k0 = ks * 16;
            uint32_t a[2][4];
            #pragma unroll
            for (int mi = 0; mi < 2; mi++) {
                int row = m0 + mi * 16;
                a[mi][0] = *reinterpret_cast<const uint32_t*>(&As[(row + g) * SK + k0 + 2 * t4]);
                a[mi][1] = *reinterpret_cast<const uint32_t*>(&As[(row + g + 8) * SK + k0 + 2 * t4]);
                a[mi][2] = *reinterpret_cast<const uint32_t*>(&As[(row + g) * SK + k0 + 2 * t4 + 8]);
                a[mi][3] = *reinterpret_cast<const uint32_t*>(&As[(row + g + 8) * SK + k0 + 2 * t4 + 8]);
            }
            #pragma unroll
            for (int ni = 0; ni < 8; ni++) {
                uint32_t b[2];
                int col = n0 + ni * 8 + g;
                b[0] = *reinterpret_cast<const uint32_t*>(&Bs[col * SK + k0 + 2 * t4]);
                b[1] = *reinterpret_cast<const uint32_t*>(&Bs[col * SK + k0 + 2 * t4 + 8]);
                mma16816(acc[0][ni], a[0], b);
                mma16816(acc[1][ni], a[1], b);
            }
        }
        __syncthreads();
    }

    // fused epilogue: exp(-2 * max(2 - 2*g, 0)), reduce, one atomic per block
    float s = 0.0f;
    #pragma unroll
    for (int mi = 0; mi < 2; mi++)
        #pragma unroll
        for (int ni = 0; ni < 8; ni++)
            #pragma unroll
            for (int e = 0; e < 4; e++) {
                float gv = acc[mi][ni][e];
                float d2 = fmaxf(2.0f - 2.0f * gv, 0.0f);
                s += __expf(-2.0f * d2);
            }
    if (bi != bj) s *= 2.0f;
    #pragma unroll
    for (int o = 16; o; o >>= 1) s += __shfl_xor_sync(0xffffffffu, s, o);
    if (lane == 0) sred[wid] = s;
    __syncthreads();
    if (tid == 0) {
        float tot = 0.f;
        #pragma unroll
        for (int i = 0; i < 8; i++) tot += sred[i];
        atomicAdd(&g_acc[1], tot);
    }
}

__global__ void k_final(float* out) {
    float align_loss = g_acc[0] / (float)BPAIRS;
    float S = g_acc[1];
    float uniform_loss = (S - (float)NROWS) / ((float)NROWS * (float)(NROWS - 1));
    out[0] = align_loss + uniform_loss;
}

extern "C" void kernel_launch(void* const* d_in, const int* in_sizes, int n_in,
                              void* d_out, int out_size) {
    const float* A = (const float*)d_in[0];
    const float* B = (const float*)d_in[1];
    float* out = (float*)d_out;

    k_zero<<<1, 1>>>();
    k_norm<<<BPAIRS, 256>>>(A, B);
    const int tiles_1d = NROWS / BM;                       // 64
    const int ntiles = tiles_1d * (tiles_1d + 1) / 2;      // 2080
    k_gram<<<ntiles, 256>>>();
    k_final<<<1, 1>>>(out);
}

// round 3
// speedup vs baseline: 1.1340x; 1.1340x over previous
#include <cuda_runtime.h>
#include <cuda_bf16.h>
#include <cstdint>

#define BPAIRS 4096
#define NROWS  8192
#define DCOLS  256

// tile config
#define TM 128
#define TN 128
#define KC 64                 // K chunk (bf16)
#define NCHUNK (DCOLS / KC)   // 4
#define SK  72                // padded smem stride in bf16 (144 B)
#define SKB 144               // stride bytes
#define TILEB (TM * SKB)      // 18432 B per operand buffer
// dynamic smem: A0 B0 A1 B1
#define SMEM_TOTAL (4 * TILEB)

__device__ __align__(16) __nv_bfloat16 g_X[NROWS * DCOLS];
__device__ float g_acc[2];

__device__ __forceinline__ uint32_t smem_u32(const void* p) {
    uint32_t a;
    asm("{ .reg .u64 t; cvta.to.shared.u64 t, %1; cvt.u32.u64 %0, t; }" : "=r"(a) : "l"(p));
    return a;
}
__device__ __forceinline__ void mma16816(float d[4], const uint32_t a[4], const uint32_t b0, const uint32_t b1) {
    asm volatile(
        "mma.sync.aligned.m16n8k16.row.col.f32.bf16.bf16.f32 "
        "{%0,%1,%2,%3}, {%4,%5,%6,%7}, {%8,%9}, {%0,%1,%2,%3};\n"
        : "+f"(d[0]), "+f"(d[1]), "+f"(d[2]), "+f"(d[3])
        : "r"(a[0]), "r"(a[1]), "r"(a[2]), "r"(a[3]), "r"(b0), "r"(b1));
}
__device__ __forceinline__ void ldsm4(uint32_t r[4], uint32_t addr) {
    asm volatile("ldmatrix.sync.aligned.m8n8.x4.shared.b16 {%0,%1,%2,%3}, [%4];"
                 : "=r"(r[0]), "=r"(r[1]), "=r"(r[2]), "=r"(r[3]) : "r"(addr));
}
__device__ __forceinline__ void cpasync16(uint32_t dst, const void* src) {
    asm volatile("cp.async.cg.shared.global [%0], [%1], 16;" :: "r"(dst), "l"(src));
}

__global__ void k_zero() { g_acc[0] = 0.0f; g_acc[1] = 0.0f; }

__global__ void k_norm(const float* __restrict__ A, const float* __restrict__ B) {
    int r = blockIdx.x;
    int t = threadIdx.x;           // 256 == DCOLS
    float a = A[r * DCOLS + t];
    float b = B[r * DCOLS + t];
    float sa = a * a, sb = b * b;
    #pragma unroll
    for (int o = 16; o; o >>= 1) {
        sa += __shfl_xor_sync(0xffffffffu, sa, o);
        sb += __shfl_xor_sync(0xffffffffu, sb, o);
    }
    __shared__ float ssa[8], ssb[8], sdd[8];
    int wid = t >> 5, lane = t & 31;
    if (lane == 0) { ssa[wid] = sa; ssb[wid] = sb; }
    __syncthreads();
    float na = 0.f, nb = 0.f;
    #pragma unroll
    for (int i = 0; i < 8; i++) { na += ssa[i]; nb += ssb[i]; }
    na = fmaxf(sqrtf(na), 1e-12f);
    nb = fmaxf(sqrtf(nb), 1e-12f);
    float an = a / na, bn = b / nb;
    g_X[r * DCOLS + t] = __float2bfloat16(an);
    g_X[(BPAIRS + r) * DCOLS + t] = __float2bfloat16(bn);
    float d = an - bn;
    float dd = d * d;
    #pragma unroll
    for (int o = 16; o; o >>= 1) dd += __shfl_xor_sync(0xffffffffu, dd, o);
    if (lane == 0) sdd[wid] = dd;
    __syncthreads();
    if (t == 0) {
        float s = 0.f;
        #pragma unroll
        for (int i = 0; i < 8; i++) s += sdd[i];
        atomicAdd(&g_acc[0], s);
    }
}

// Gram over upper-triangular block grid (bj >= bi), 128x128 tiles,
// ldmatrix + mma.sync bf16, cp.async double-buffered K streaming.
__global__ __launch_bounds__(256, 2) void k_gram() {
    extern __shared__ __align__(128) char smem[];
    __shared__ float sred[8];
    uint32_t sb = smem_u32(smem);

    int tid = threadIdx.x;
    int wid = tid >> 5, lane = tid & 31;
    int wm = wid >> 1, wn = wid & 1;
    int m0 = wm * 32, n0 = wn * 64;

    // decode (bi, bj), bj >= bi
    int bi = 0, rem = blockIdx.x, rowlen = NROWS / TM;
    while (rem >= rowlen) { rem -= rowlen; bi++; rowlen--; }
    int bj = bi + rem;
    int ai0 = bi * TM, bj0 = bj * TN;

    // hoisted per-lane fragment addresses (offsets within a buffer)
    // A ldmatrix.x4: lanes 0-15 -> rows m0+(lane&15) @k0, lanes 16-31 -> same rows @k0+8
    uint32_t a_off = (uint32_t)((m0 + (lane & 15)) * SKB + ((lane >> 4) << 4)); // koff 8 bf16 = 16B
    // B ldmatrix.x4: m0: n0..7@k0, m1: n0..7@k8, m2: n8..15@k0, m3: n8..15@k8
    int bn = (lane & 7) + ((lane >> 4) << 3);
    uint32_t b_off = (uint32_t)((n0 + bn) * SKB + ((lane & 8) ? 16 : 0));

    // staging indices: 4 iters x 256 thr cover 1024 chunks of 16B per operand
    int sr = 0, su = 0; // computed in loop

    float acc[2][8][4];
    #pragma unroll
    for (int mi = 0; mi < 2; mi++)
        #pragma unroll
        for (int ni = 0; ni < 8; ni++)
            #pragma unroll
            for (int e = 0; e < 4; e++) acc[mi][ni][e] = 0.0f;

    // prologue: stage chunks 0 and 1
    #pragma unroll
    for (int c = 0; c < 2; c++) {
        uint32_t ab = sb + (2 * c + 0) * TILEB;
        uint32_t bb = sb + (2 * c + 1) * TILEB;
        const __nv_bfloat16* ga = &g_X[(size_t)ai0 * DCOLS + c * KC];
        const __nv_bfloat16* gb = &g_X[(size_t)bj0 * DCOLS + c * KC];
        #pragma unroll
        for (int i = 0; i < 4; i++) {
            int idx = tid + i * 256;
            sr = idx >> 3; su = idx & 7;
            cpasync16(ab + sr * SKB + su * 16, ga + (size_t)sr * DCOLS + su * 8);
            cpasync16(bb + sr * SKB + su * 16, gb + (size_t)sr * DCOLS + su * 8);
        }
        asm volatile("cp.async.commit_group;" ::: "memory");
    }

    #pragma unroll
    for (int c = 0; c < NCHUNK; c++) {
        if (c == 3) asm volatile("cp.async.wait_group 0;" ::: "memory");
        else        asm volatile("cp.async.wait_group 1;" ::: "memory");
        __syncthreads();

        uint32_t abase = sb + (2 * (c & 1) + 0) * TILEB + a_off;
        uint32_t bbase = sb + (2 * (c & 1) + 1) * TILEB + b_off;

        #pragma unroll
        for (int ks = 0; ks < KC / 16; ks++) {
            uint32_t a0[4], a1[4];
            ldsm4(a0, abase + ks * 32);
            ldsm4(a1, abase + 16 * SKB + ks * 32);
            #pragma unroll
            for (int nb = 0; nb < 4; nb++) {
                uint32_t bf[4];
                ldsm4(bf, bbase + nb * 16 * SKB + ks * 32);
                mma16816(acc[0][2 * nb + 0], a0, bf[0], bf[1]);
                mma16816(acc[0][2 * nb + 1], a0, bf[2], bf[3]);
                mma16816(acc[1][2 * nb + 0], a1, bf[0], bf[1]);
                mma16816(acc[1][2 * nb + 1], a1, bf[2], bf[3]);
            }
        }
        __syncthreads();

        if (c < 2) {
            int cn = c + 2;
            uint32_t ab = sb + (2 * (cn & 1) + 0) * TILEB;
            uint32_t bb = sb + (2 * (cn & 1) + 1) * TILEB;
            const __nv_bfloat16* ga = &g_X[(size_t)ai0 * DCOLS + cn * KC];
            const __nv_bfloat16* gb = &g_X[(size_t)bj0 * DCOLS + cn * KC];
            #pragma unroll
            for (int i = 0; i < 4; i++) {
                int idx = tid + i * 256;
                sr = idx >> 3; su = idx & 7;
                cpasync16(ab + sr * SKB + su * 16, ga + (size_t)sr * DCOLS + su * 8);
                cpasync16(bb + sr * SKB + su * 16, gb + (size_t)sr * DCOLS + su * 8);
            }
            asm volatile("cp.async.commit_group;" ::: "memory");
        }
    }

    // epilogue: exp(min(4g-4, 0)), reduce, one atomic per block
    float s = 0.0f;
    #pragma unroll
    for (int mi = 0; mi < 2; mi++)
        #pragma unroll
        for (int ni = 0; ni < 8; ni++)
            #pragma unroll
            for (int e = 0; e < 4; e++) {
                float gv = acc[mi][ni][e];
                float t = fminf(4.0f * gv - 4.0f, 0.0f);
                s += __expf(t);
            }
    if (bi != bj) s *= 2.0f;
    #pragma unroll
    for (int o = 16; o; o >>= 1) s += __shfl_xor_sync(0xffffffffu, s, o);
    if (lane == 0) sred[wid] = s;
    __syncthreads();
    if (tid == 0) {
        float tot = 0.f;
        #pragma unroll
        for (int i = 0; i < 8; i++) tot += sred[i];
        atomicAdd(&g_acc[1], tot);
    }
}

__global__ void k_final(float* out) {
    float align_loss = g_acc[0] / (float)BPAIRS;
    float S = g_acc[1];
    float uniform_loss = (S - (float)NROWS) / ((float)NROWS * (float)(NROWS - 1));
    out[0] = align_loss + uniform_loss;
}

extern "C" void kernel_launch(void* const* d_in, const int* in_sizes, int n_in,
                              void* d_out, int out_size) {
    const float* A = (const float*)d_in[0];
    const float* B = (const float*)d_in[1];
    float* out = (float*)d_out;

    cudaFuncSetAttribute(k_gram, cudaFuncAttributeMaxDynamicSharedMemorySize, SMEM_TOTAL);

    k_zero<<<1, 1>>>();
    k_norm<<<BPAIRS, 256>>>(A, B);
    const int tiles_1d = NROWS / TM;                       // 64
    const int ntiles = tiles_1d * (tiles_1d + 1) / 2;      // 2080
    k_gram<<<ntiles, 256, SMEM_TOTAL>>>();
    k_final<<<1, 1>>>(out);
}